// round 17
// baseline (speedup 1.0000x reference)
#include <cuda_runtime.h>
#include <cstdint>

// Problem constants
#define NNODES 100000
#define NEDGES 1600000
#define HEADS  8
#define HD     128               // HEADS*OUTD = 8*16
#define EH     (NEDGES*HEADS)    // 12,800,000
#define NPROJ  (NNODES*HD)       // 12,800,000
#define CAP    64                // bucket capacity (Poisson(16): P(deg>63) ~ 1e-21/node)
#define EB     128               // edges per elogit-role block
#define GB_GEMM 782              // gemm-role blocks (782*128 >= NNODES)
#define GB_ELOG (NEDGES / EB)    // 12500
#define GB_MAIN (GB_GEMM + GB_ELOG)

// Device scratch (no allocation allowed anywhere).
// g_cnt is zero at module load; k_agg restores it to zero after each use,
// so every kernel_launch call (and graph replay) sees zeroed counters.
__device__ float g_feat_proj[NPROJ];
__device__ float g_eexp[EH];             // exp(logit) per (edge, head)
__device__ int   g_cnt[NNODES];
__device__ int   g_bucket[NNODES * CAP];
__device__ float g_a_fallback[EH];       // used only if out buffer holds rst alone

// ---------------------------------------------------------------------------
// Fused main kernel: gemm-role blocks and elogit-role blocks co-resident.
// gemm is fma-issue/latency bound; elogit is DRAM-stream bound -> overlap.
// gemm roles are every 16th bid so both populations mix from wave 1.
// ---------------------------------------------------------------------------
__global__ __launch_bounds__(256) void k_main(const float* __restrict__ A,
                                              const float* __restrict__ B,
                                              const float* __restrict__ e_feat,
                                              const float* __restrict__ W_e,
                                              const int*   __restrict__ dst) {
    __shared__ __align__(16) char smem_buf[35072];  // max(gemm 16640, elogit 35072)

    const int bid = blockIdx.x;
    const int tid = threadIdx.x;
    const bool is_gemm = ((bid & 15) == 0) && ((bid >> 4) < GB_GEMM);

    if (is_gemm) {
        // ----- GEMM role: g_feat_proj = feat @ W, BM=128 tile -----
        float (*sA)[132] = (float (*)[132])smem_buf;             // 8448 B
        float4 (*sB4)[32] = (float4 (*)[32])(smem_buf + 8448);   // 8192 B

        const int row0 = (bid >> 4) * 128;
        const int tx   = tid & 15;
        const int ty   = tid >> 4;
        const int lrow = tid & 127;
        const int lq   = tid >> 7;

        unsigned long long acc2[4][8];
#pragma unroll
        for (int ip = 0; ip < 4; ip++)
#pragma unroll
            for (int j = 0; j < 8; j++) acc2[ip][j] = 0ull;

        for (int k0 = 0; k0 < 128; k0 += 16) {
            float4 av0 = make_float4(0.f, 0.f, 0.f, 0.f);
            float4 av1 = av0;
            int ar = row0 + lrow;
            if (ar < NNODES) {
                const float* ap = A + (size_t)ar * 128 + k0 + lq * 8;
                av0 = *(const float4*)ap;
                av1 = *(const float4*)(ap + 4);
            }
            sA[lq * 8 + 0][lrow] = av0.x;
            sA[lq * 8 + 1][lrow] = av0.y;
            sA[lq * 8 + 2][lrow] = av0.z;
            sA[lq * 8 + 3][lrow] = av0.w;
            sA[lq * 8 + 4][lrow] = av1.x;
            sA[lq * 8 + 5][lrow] = av1.y;
            sA[lq * 8 + 6][lrow] = av1.z;
            sA[lq * 8 + 7][lrow] = av1.w;
#pragma unroll
            for (int p = 0; p < 2; p++) {
                int fi = tid + p * 256;
                int kk = fi >> 5, n4 = fi & 31;
                sB4[kk][n4] = ((const float4*)B)[(k0 + kk) * 32 + n4];
            }
            __syncthreads();
#pragma unroll
            for (int k = 0; k < 16; k++) {
                ulonglong2 aA = *(const ulonglong2*)&sA[k][ty * 8];
                ulonglong2 aB = *(const ulonglong2*)&sA[k][ty * 8 + 4];
                unsigned long long apr[4] = {aA.x, aA.y, aB.x, aB.y};
                float4 b0 = sB4[k][tx];
                float4 b1 = sB4[k][tx + 16];
                float bs[8] = {b0.x, b0.y, b0.z, b0.w, b1.x, b1.y, b1.z, b1.w};
                unsigned long long bd[8];
#pragma unroll
                for (int j = 0; j < 8; j++)
                    asm("mov.b64 %0, {%1,%1};" : "=l"(bd[j]) : "f"(bs[j]));
#pragma unroll
                for (int ip = 0; ip < 4; ip++)
#pragma unroll
                    for (int j = 0; j < 8; j++)
                        asm("fma.rn.f32x2 %0, %1, %2, %0;"
                            : "+l"(acc2[ip][j]) : "l"(apr[ip]), "l"(bd[j]));
            }
            __syncthreads();
        }
#pragma unroll
        for (int ip = 0; ip < 4; ip++) {
            float lo[8], hi[8];
#pragma unroll
            for (int j = 0; j < 8; j++)
                asm("mov.b64 {%0,%1}, %2;" : "=f"(lo[j]), "=f"(hi[j]) : "l"(acc2[ip][j]));
            int r0r = row0 + ty * 8 + 2 * ip;
            if (r0r < NNODES) {
                ((float4*)g_feat_proj)[(size_t)r0r * 32 + tx]      = make_float4(lo[0], lo[1], lo[2], lo[3]);
                ((float4*)g_feat_proj)[(size_t)r0r * 32 + 16 + tx] = make_float4(lo[4], lo[5], lo[6], lo[7]);
            }
            int r1r = r0r + 1;
            if (r1r < NNODES) {
                ((float4*)g_feat_proj)[(size_t)r1r * 32 + tx]      = make_float4(hi[0], hi[1], hi[2], hi[3]);
                ((float4*)g_feat_proj)[(size_t)r1r * 32 + 16 + tx] = make_float4(hi[4], hi[5], hi[6], hi[7]);
            }
        }
    } else {
        // ----- ELOGIT role: exp(e_feat @ W_e) + bucket fill -----
        // 256 threads, 128 edges: thread = (edge = tid&127, half = tid>>7).
        // Each thread computes 4 heads (half*4..half*4+3) via 2 FFMA2 per k.
        float (*sET)[129] = (float (*)[129])smem_buf;            // 33024 B
        float* sW = (float*)(smem_buf + 33024);                   // 2048 B

        const int eb = bid - (((bid >> 4) < GB_GEMM) ? (bid >> 4) + 1 : GB_GEMM);
        const int e0 = eb * EB;

        sW[tid]       = W_e[tid];
        sW[tid + 256] = W_e[tid + 256];

        const float4* ef4 = (const float4*)(e_feat + (size_t)e0 * 64);
#pragma unroll
        for (int i = 0; i < 8; i++) {
            int j = i * 256 + tid;
            float4 v = ef4[j];
            int edge = j >> 4, chunk = j & 15;
            sET[chunk * 4 + 0][edge] = v.x;
            sET[chunk * 4 + 1][edge] = v.y;
            sET[chunk * 4 + 2][edge] = v.z;
            sET[chunk * 4 + 3][edge] = v.w;
        }
        __syncthreads();

        const int edge = tid & 127;
        const int half = tid >> 7;            // uniform per warp

        unsigned long long aLo = 0ull, aHi = 0ull;
#pragma unroll
        for (int k = 0; k < 64; k++) {
            float ef = sET[k][edge];
            unsigned long long ef2;
            asm("mov.b64 %0, {%1,%1};" : "=l"(ef2) : "f"(ef));
            ulonglong2 w = *(const ulonglong2*)&sW[k * 8 + half * 4];
            asm("fma.rn.f32x2 %0, %1, %2, %0;" : "+l"(aLo) : "l"(ef2), "l"(w.x));
            asm("fma.rn.f32x2 %0, %1, %2, %0;" : "+l"(aHi) : "l"(ef2), "l"(w.y));
        }
        float s0, s1, s2, s3;
        asm("mov.b64 {%0,%1}, %2;" : "=f"(s0), "=f"(s1) : "l"(aLo));
        asm("mov.b64 {%0,%1}, %2;" : "=f"(s2), "=f"(s3) : "l"(aHi));

        const int e = e0 + edge;
        ((float4*)g_eexp)[(size_t)e * 2 + half] =
            make_float4(__expf(s0), __expf(s1), __expf(s2), __expf(s3));

        if (half == 0) {
            int d   = dst[e];
            int pos = atomicAdd(&g_cnt[d], 1);
            if (pos < CAP) g_bucket[d * CAP + pos] = e;
        }
    }
}

// ---------------------------------------------------------------------------
// Warp-per-dst-node FUSED aggregation (unnormalized accumulate + late scale).
// Also resets g_cnt[d] = 0 for the next kernel_launch call / graph replay.
// ---------------------------------------------------------------------------
__global__ __launch_bounds__(256) void k_agg(const int* __restrict__ src,
                                             float* __restrict__ rst,
                                             float* __restrict__ a_out) {
    __shared__ float sL[8][CAP * 8];          // 16 KB: ex values
    __shared__ int   sEid[8][CAP];            // 2 KB
    __shared__ int   sSrc[8][CAP];            // 2 KB

    const int warp = threadIdx.x >> 5;
    const int lane = threadIdx.x & 31;
    const int d    = blockIdx.x * 8 + warp;
    if (d >= NNODES) return;

    const int h = lane >> 2;
    const int c = lane & 3;
    float* L = sL[warp];

    int g = g_cnt[d];
    if (g > CAP) g = CAP;
    if (lane == 0) g_cnt[d] = 0;      // restore invariant for next launch

    // Phase 1: all lanes cooperatively load bucket ids + src ids (parallel).
#pragma unroll
    for (int i0 = 0; i0 < CAP; i0 += 32) {
        int i = i0 + lane;
        if (i < g) {
            int e = g_bucket[d * CAP + i];
            sEid[warp][i] = e;
            sSrc[warp][i] = src[e];
        }
    }
    __syncwarp();

    // Phase 2: fused gather + unnormalized accumulate + denominator.
    float4 acc = make_float4(0.f, 0.f, 0.f, 0.f);
    float  den = 0.f;
    const float4* gp = (const float4*)g_feat_proj;
    const int* eidw = sEid[warp];
    const int* srcw = sSrc[warp];

    int i = 0;
    for (; i + 4 <= g; i += 4) {
        int s0 = srcw[i], s1 = srcw[i + 1], s2 = srcw[i + 2], s3 = srcw[i + 3];
        float e0 = g_eexp[(size_t)eidw[i + 0] * 8 + h];
        float e1 = g_eexp[(size_t)eidw[i + 1] * 8 + h];
        float e2 = g_eexp[(size_t)eidw[i + 2] * 8 + h];
        float e3 = g_eexp[(size_t)eidw[i + 3] * 8 + h];
        float4 f0 = gp[(size_t)s0 * 32 + lane];
        float4 f1 = gp[(size_t)s1 * 32 + lane];
        float4 f2 = gp[(size_t)s2 * 32 + lane];
        float4 f3 = gp[(size_t)s3 * 32 + lane];
        if (c == 0) {
            L[(i + 0) * 8 + h] = e0;
            L[(i + 1) * 8 + h] = e1;
            L[(i + 2) * 8 + h] = e2;
            L[(i + 3) * 8 + h] = e3;
        }
        den += (e0 + e1) + (e2 + e3);
        acc.x += f0.x * e0 + f1.x * e1 + f2.x * e2 + f3.x * e3;
        acc.y += f0.y * e0 + f1.y * e1 + f2.y * e2 + f3.y * e3;
        acc.z += f0.z * e0 + f1.z * e1 + f2.z * e2 + f3.z * e3;
        acc.w += f0.w * e0 + f1.w * e1 + f2.w * e2 + f3.w * e3;
    }
    for (; i < g; i++) {
        int s = srcw[i];
        float ex = g_eexp[(size_t)eidw[i] * 8 + h];
        if (c == 0) L[i * 8 + h] = ex;
        den += ex;
        float4 fp = gp[(size_t)s * 32 + lane];
        acc.x += fp.x * ex; acc.y += fp.y * ex;
        acc.z += fp.z * ex; acc.w += fp.w * ex;
    }

    // Phase 3: scale once; store rst; emit a = ex * rden.
    // (attn_sum = sum(a) == 1 to fp32 roundoff, so rst = acc * rden directly)
    float rden = 1.f / den;
    acc.x *= rden; acc.y *= rden; acc.z *= rden; acc.w *= rden;
    ((float4*)rst)[(size_t)d * 32 + lane] = acc;

    __syncwarp();
    float* ap = a_out ? a_out : g_a_fallback;
    for (int j = c; j < g; j += 4)
        ap[(size_t)eidw[j] * 8 + h] = L[j * 8 + h] * rden;
}

// ---------------------------------------------------------------------------
extern "C" void kernel_launch(void* const* d_in, const int* in_sizes, int n_in,
                              void* d_out, int out_size) {
    const float* feat   = (const float*)d_in[0];
    const float* e_feat = (const float*)d_in[1];
    const float* W      = (const float*)d_in[2];
    const float* W_e    = (const float*)d_in[3];
    const int*   src    = (const int*)d_in[4];
    const int*   dst    = (const int*)d_in[5];

    float* rst   = (float*)d_out;
    float* a_out = (out_size >= NPROJ + EH) ? rst + NPROJ : nullptr;

    k_main<<<GB_MAIN, 256>>>(feat, W, e_feat, W_e, dst);
    k_agg <<<(NNODES + 7) / 8, 256>>>(src, rst, a_out);
}